// round 1
// baseline (speedup 1.0000x reference)
#include <cuda_runtime.h>
#include <cuda_bf16.h>
#include <math.h>

#define NN 50000
#define NE 800000
#define DD 128
#define NG 64
#define NC 2
#define SLOPE 0.2f

// ---------------- scratch (static device globals; no allocation) ----------------
__device__ float g_Wh[NN * DD];
__device__ float g_hA[NN * DD];
__device__ float g_hB[NN * DD];
__device__ float g_el[NN];
__device__ float g_er[NN];
__device__ int   g_rowptr[NN + 1];
__device__ int   g_fill[NN];
__device__ int   g_cnt[NN];
__device__ int   g_csrc[NE];
__device__ float g_hg[NG * DD];
__device__ int   g_gstart[NG + 1];

// ---------------- helpers ----------------
__device__ __forceinline__ float eluf(float x) { return x > 0.f ? x : (__expf(x) - 1.f); }
__device__ __forceinline__ float lrelu(float x) { return x > 0.f ? x : SLOPE * x; }

// ---------------- CSR build ----------------
__global__ void k_zero_cnt() {
    int i = blockIdx.x * blockDim.x + threadIdx.x;
    if (i < NN) g_cnt[i] = 0;
}

__global__ void k_hist(const int* __restrict__ dst) {
    int i = blockIdx.x * blockDim.x + threadIdx.x;
    if (i < NE) atomicAdd(&g_cnt[dst[i]], 1);
}

// single-block exclusive scan over g_cnt -> g_rowptr, g_fill
__global__ void k_scan() {
    __shared__ int sums[1024];
    int tid = threadIdx.x;
    const int chunk = (NN + 1023) / 1024;  // 49
    int start = tid * chunk;
    int end = min(start + chunk, NN);
    int s = 0;
    for (int i = start; i < end; i++) s += g_cnt[i];
    sums[tid] = s;
    __syncthreads();
    for (int off = 1; off < 1024; off <<= 1) {
        int v = (tid >= off) ? sums[tid - off] : 0;
        __syncthreads();
        sums[tid] += v;
        __syncthreads();
    }
    int run = (tid == 0) ? 0 : sums[tid - 1];
    for (int i = start; i < end; i++) {
        g_rowptr[i] = run;
        g_fill[i] = run;
        run += g_cnt[i];
    }
    if (tid == 0) g_rowptr[NN] = sums[1023];
}

__global__ void k_fillcsr(const int* __restrict__ src, const int* __restrict__ dst) {
    int i = blockIdx.x * blockDim.x + threadIdx.x;
    if (i < NE) {
        int d = dst[i];
        int p = atomicAdd(&g_fill[d], 1);
        g_csrc[p] = src[i];
    }
}

// ---------------- GEMM: C[M,128] = A[M,128] @ W[128,128] ----------------
__global__ void __launch_bounds__(256, 2)
k_gemm(const float* __restrict__ A, const float* __restrict__ W, float* __restrict__ C, int M) {
    __shared__ float As[32][132];  // [k][m], padded
    __shared__ float Bs[32][128];  // [k][n]
    int tid = threadIdx.x;
    int row0 = blockIdx.x * 128;
    float acc[8][8];
#pragma unroll
    for (int i = 0; i < 8; i++)
#pragma unroll
        for (int j = 0; j < 8; j++) acc[i][j] = 0.f;

    int aCol4 = tid & 7;    // k/4 within 8
    int aRow = tid >> 3;    // 0..31
    int bCol4 = tid & 31;   // n/4
    int bRow = tid >> 5;    // 0..7
    int ty = tid >> 4, tx = tid & 15;

    for (int k0 = 0; k0 < 128; k0 += 32) {
#pragma unroll
        for (int i = 0; i < 4; i++) {
            int r = aRow + 32 * i;
            int gr = row0 + r;
            float4 v = make_float4(0.f, 0.f, 0.f, 0.f);
            if (gr < M) v = *(const float4*)(A + (size_t)gr * 128 + k0 + aCol4 * 4);
            As[aCol4 * 4 + 0][r] = v.x;
            As[aCol4 * 4 + 1][r] = v.y;
            As[aCol4 * 4 + 2][r] = v.z;
            As[aCol4 * 4 + 3][r] = v.w;
        }
#pragma unroll
        for (int i = 0; i < 4; i++) {
            int kr = bRow + 8 * i;
            *(float4*)(&Bs[kr][bCol4 * 4]) = *(const float4*)(W + (k0 + kr) * 128 + bCol4 * 4);
        }
        __syncthreads();
#pragma unroll
        for (int k = 0; k < 32; k++) {
            float a[8], b[8];
#pragma unroll
            for (int i = 0; i < 8; i++) a[i] = As[k][ty * 8 + i];
#pragma unroll
            for (int j = 0; j < 8; j++) b[j] = Bs[k][tx * 8 + j];
#pragma unroll
            for (int i = 0; i < 8; i++)
#pragma unroll
                for (int j = 0; j < 8; j++) acc[i][j] += a[i] * b[j];
        }
        __syncthreads();
    }
#pragma unroll
    for (int i = 0; i < 8; i++) {
        int gr = row0 + ty * 8 + i;
        if (gr < M) {
            float4 v0 = make_float4(acc[i][0], acc[i][1], acc[i][2], acc[i][3]);
            float4 v1 = make_float4(acc[i][4], acc[i][5], acc[i][6], acc[i][7]);
            *(float4*)(C + (size_t)gr * 128 + tx * 8) = v0;
            *(float4*)(C + (size_t)gr * 128 + tx * 8 + 4) = v1;
        }
    }
}

// ---------------- per-node attention scores el/er ----------------
__global__ void k_scores(const float* __restrict__ Wh, const float* __restrict__ al,
                         const float* __restrict__ ar) {
    int w = (blockIdx.x * blockDim.x + threadIdx.x) >> 5;
    int lane = threadIdx.x & 31;
    if (w >= NN) return;
    float4 v = ((const float4*)Wh)[(size_t)w * 32 + lane];
    float4 a = ((const float4*)al)[lane];
    float4 r = ((const float4*)ar)[lane];
    float sl = v.x * a.x + v.y * a.y + v.z * a.z + v.w * a.w;
    float sr = v.x * r.x + v.y * r.y + v.z * r.z + v.w * r.w;
#pragma unroll
    for (int o = 16; o > 0; o >>= 1) {
        sl += __shfl_xor_sync(0xFFFFFFFFu, sl, o);
        sr += __shfl_xor_sync(0xFFFFFFFFu, sr, o);
    }
    if (lane == 0) {
        g_el[w] = sl;
        g_er[w] = sr;
    }
}

// ---------------- warp-per-dst softmax + aggregation ----------------
__global__ void k_aggregate(const float* __restrict__ Wh, const float* __restrict__ bias,
                            float* __restrict__ hout) {
    int node = (blockIdx.x * blockDim.x + threadIdx.x) >> 5;
    int lane = threadIdx.x & 31;
    if (node >= NN) return;
    int start = g_rowptr[node];
    int end = g_rowptr[node + 1];
    float erd = g_er[node];

    // online softmax: running max m, running sum s (of exp(e - m))
    float m = -INFINITY, s = 0.f;
    for (int base = start; base < end; base += 32) {
        int idx = base + lane;
        float e = -INFINITY;
        if (idx < end) {
            int sv = g_csrc[idx];
            e = lrelu(g_el[sv] + erd);
        }
        float cm = e;
#pragma unroll
        for (int o = 16; o > 0; o >>= 1) cm = fmaxf(cm, __shfl_xor_sync(0xFFFFFFFFu, cm, o));
        float nm = fmaxf(m, cm);
        float ex = __expf(e - nm);  // e=-inf -> 0
#pragma unroll
        for (int o = 16; o > 0; o >>= 1) ex += __shfl_xor_sync(0xFFFFFFFFu, ex, o);
        float scale = (m == -INFINITY) ? 0.f : __expf(m - nm);
        s = s * scale + ex;
        m = nm;
    }
    float inv_s = (end > start) ? 1.f / s : 0.f;

    float4 acc = make_float4(0.f, 0.f, 0.f, 0.f);
    const float4* Wh4 = (const float4*)Wh;
    for (int idx = start; idx < end; idx++) {
        int sv = g_csrc[idx];  // uniform across warp -> broadcast
        float t = lrelu(g_el[sv] + erd);
        float a = __expf(t - m) * inv_s;
        float4 w = Wh4[(size_t)sv * 32 + lane];
        acc.x += a * w.x;
        acc.y += a * w.y;
        acc.z += a * w.z;
        acc.w += a * w.w;
    }
    float4 b4 = ((const float4*)bias)[lane];
    float4 o;
    o.x = eluf(acc.x + b4.x);
    o.y = eluf(acc.y + b4.y);
    o.z = eluf(acc.z + b4.z);
    o.w = eluf(acc.w + b4.w);
    ((float4*)hout)[(size_t)node * 32 + lane] = o;
}

// ---------------- graph pooling + classifier ----------------
__global__ void k_bounds(const int* __restrict__ gid) {
    int g = threadIdx.x;
    if (g > NG) return;
    int lo = 0, hi = NN;
    while (lo < hi) {
        int mid = (lo + hi) >> 1;
        if (gid[mid] < g) lo = mid + 1; else hi = mid;
    }
    g_gstart[g] = lo;
}

__global__ void k_pool(const float* __restrict__ h) {
    int g = blockIdx.x;
    int t = threadIdx.x;
    int st = g_gstart[g], en = g_gstart[g + 1];
    float s = 0.f;
    for (int i = st; i < en; i++) s += h[(size_t)i * DD + t];
    int c = en - st;
    g_hg[g * DD + t] = s / (float)max(c, 1);
}

__global__ void k_classify(const float* __restrict__ Wc, const float* __restrict__ bc,
                           float* __restrict__ out) {
    int t = threadIdx.x;  // 128 threads, one per (graph, class)
    if (t >= NG * NC) return;
    int g = t >> 1, c = t & 1;
    float s = 0.f;
#pragma unroll 4
    for (int k = 0; k < DD; k++) s += g_hg[g * DD + k] * Wc[k * NC + c];
    out[g * NC + c] = s + bc[c];
}

// ---------------- launch ----------------
extern "C" void kernel_launch(void* const* d_in, const int* in_sizes, int n_in,
                              void* d_out, int out_size) {
    const float* x = (const float*)d_in[0];
    const int* src = (const int*)d_in[1];
    const int* dst = (const int*)d_in[2];
    const int* gid = (const int*)d_in[3];
    const float* W[3]  = {(const float*)d_in[4],  (const float*)d_in[8],  (const float*)d_in[12]};
    const float* al[3] = {(const float*)d_in[5],  (const float*)d_in[9],  (const float*)d_in[13]};
    const float* ar[3] = {(const float*)d_in[6],  (const float*)d_in[10], (const float*)d_in[14]};
    const float* bb[3] = {(const float*)d_in[7],  (const float*)d_in[11], (const float*)d_in[15]};
    const float* Wc = (const float*)d_in[16];
    const float* bc = (const float*)d_in[17];
    float* out = (float*)d_out;

    float *pWh, *phA, *phB;
    cudaGetSymbolAddress((void**)&pWh, g_Wh);
    cudaGetSymbolAddress((void**)&phA, g_hA);
    cudaGetSymbolAddress((void**)&phB, g_hB);

    // CSR build (per launch; deterministic up to fp summation order)
    k_zero_cnt<<<(NN + 255) / 256, 256>>>();
    k_hist<<<(NE + 255) / 256, 256>>>(dst);
    k_scan<<<1, 1024>>>();
    k_fillcsr<<<(NE + 255) / 256, 256>>>(src, dst);

    const int warpGrid = (NN * 32 + 255) / 256;
    const float* hin = x;
    float* bufs[2] = {phA, phB};
    for (int l = 0; l < 3; l++) {
        k_gemm<<<(NN + 127) / 128, 256>>>(hin, W[l], pWh, NN);
        k_scores<<<warpGrid, 256>>>(pWh, al[l], ar[l]);
        k_aggregate<<<warpGrid, 256>>>(pWh, bb[l], bufs[l & 1]);
        hin = bufs[l & 1];
    }

    k_bounds<<<1, 128>>>(gid);
    k_pool<<<NG, 128>>>(hin);
    k_classify<<<1, 128>>>(Wc, bc, out);
}

// round 4
// speedup vs baseline: 1.3313x; 1.3313x over previous
#include <cuda_runtime.h>
#include <math.h>
#include <stdint.h>

#define NN 50000
#define NE 800000
#define DD 128
#define NG 64
#define NC 2
#define SLOPE 0.2f

// ---------------- scratch (static device globals; no allocation) ----------------
__device__ float g_Wh[NN * DD];
__device__ float g_hA[NN * DD];
__device__ float g_hB[NN * DD];
__device__ float g_el[NN];
__device__ float g_er[NN];
__device__ int   g_rowptr[NN + 1];
__device__ int   g_fill[NN];
__device__ int   g_cnt[NN];
__device__ int   g_csrc[NE];
__device__ float g_hg[NG * DD];
__device__ int   g_gstart[NG + 1];

// ---------------- helpers ----------------
__device__ __forceinline__ float eluf(float x) { return x > 0.f ? x : (__expf(x) - 1.f); }
__device__ __forceinline__ float lrelu(float x) { return x > 0.f ? x : SLOPE * x; }
__device__ __forceinline__ float totf32(float x) {
    uint32_t r;
    asm("cvt.rna.tf32.f32 %0, %1;" : "=r"(r) : "f"(x));
    return __uint_as_float(r);
}

// ---------------- CSR build ----------------
__global__ void k_hist(const int* __restrict__ dst) {
    int i = blockIdx.x * blockDim.x + threadIdx.x;
    if (i < NE) atomicAdd(&g_cnt[dst[i]], 1);
}

__global__ void k_scan() {
    __shared__ int sums[1024];
    int tid = threadIdx.x;
    const int chunk = (NN + 1023) / 1024;
    int start = tid * chunk;
    int end = min(start + chunk, NN);
    int s = 0;
    for (int i = start; i < end; i++) s += g_cnt[i];
    sums[tid] = s;
    __syncthreads();
    for (int off = 1; off < 1024; off <<= 1) {
        int v = (tid >= off) ? sums[tid - off] : 0;
        __syncthreads();
        sums[tid] += v;
        __syncthreads();
    }
    int run = (tid == 0) ? 0 : sums[tid - 1];
    for (int i = start; i < end; i++) {
        g_rowptr[i] = run;
        g_fill[i] = run;
        run += g_cnt[i];
    }
    if (tid == 0) g_rowptr[NN] = sums[1023];
}

__global__ void k_fillcsr(const int* __restrict__ src, const int* __restrict__ dst) {
    int i = blockIdx.x * blockDim.x + threadIdx.x;
    if (i < NE) {
        int d = dst[i];
        int p = atomicAdd(&g_fill[d], 1);
        g_csrc[p] = src[i];
    }
}

// ---------------- TF32 warp-MMA GEMM + fused el/er ----------------
// C[M,128] = A[M,128] @ W[128,128]; el = C@al, er = C@ar.
// 256 threads = 8 warps in a 2(M) x 4(N) grid; warp tile 64x32; mma m16n8k8.
#define AS_STRIDE 68   // As[128][68] floats (k-chunk 64 + pad 4)
#define WS_STRIDE 136  // Ws[64][136] floats (n 128 + pad 8)
#define SMEM_FLOATS (128 * AS_STRIDE + 64 * WS_STRIDE)

__global__ void __launch_bounds__(256, 2)
k_gemm_mma(const float* __restrict__ A, const float* __restrict__ W,
           const float* __restrict__ al, const float* __restrict__ ar,
           float* __restrict__ C, int M) {
    extern __shared__ float sm[];
    float* As = sm;                      // [128][AS_STRIDE]
    float* Ws = sm + 128 * AS_STRIDE;    // [64][WS_STRIDE]
    __shared__ float s_al[DD], s_ar[DD];

    int tid = threadIdx.x;
    int wid = tid >> 5, lane = tid & 31;
    int g = lane >> 2, qa = lane & 3;    // groupID, threadID_in_group
    int wr = wid >> 2, wc = wid & 3;     // warp row(0..1) / col(0..3)
    int row0 = blockIdx.x * 128;

    if (tid < 128) {
        s_al[tid] = al[tid];
        s_ar[tid] = ar[tid];
    }

    float acc[4][4][4];
#pragma unroll
    for (int i = 0; i < 4; i++)
#pragma unroll
        for (int j = 0; j < 4; j++)
#pragma unroll
            for (int k = 0; k < 4; k++) acc[i][j][k] = 0.f;

    for (int kc = 0; kc < 2; kc++) {
        // load A chunk: rows 0..127, k cols kc*64..+64
#pragma unroll
        for (int i = 0; i < 8; i++) {
            int idx = i * 256 + tid;
            int m = idx >> 4, kq = idx & 15;
            int gr = row0 + m;
            float4 v = make_float4(0.f, 0.f, 0.f, 0.f);
            if (gr < M) v = *(const float4*)(A + (size_t)gr * 128 + kc * 64 + kq * 4);
            float* p = As + m * AS_STRIDE + kq * 4;
            p[0] = totf32(v.x); p[1] = totf32(v.y); p[2] = totf32(v.z); p[3] = totf32(v.w);
        }
        // load W chunk (no transpose): rows k = kc*64..+64, all 128 n
#pragma unroll
        for (int i = 0; i < 8; i++) {
            int idx = i * 256 + tid;
            int k = idx >> 5, nq = idx & 31;
            float4 v = *(const float4*)(W + (size_t)(kc * 64 + k) * 128 + nq * 4);
            float* p = Ws + k * WS_STRIDE + nq * 4;
            p[0] = totf32(v.x); p[1] = totf32(v.y); p[2] = totf32(v.z); p[3] = totf32(v.w);
        }
        __syncthreads();

#pragma unroll
        for (int ks = 0; ks < 8; ks++) {
            int k0 = ks * 8;
            float af[4][4];
#pragma unroll
            for (int mf = 0; mf < 4; mf++) {
                const float* base = As + (wr * 64 + mf * 16 + g) * AS_STRIDE + k0 + qa;
                af[mf][0] = base[0];
                af[mf][1] = base[8 * AS_STRIDE];
                af[mf][2] = base[4];
                af[mf][3] = base[8 * AS_STRIDE + 4];
            }
            float bf[4][2];
#pragma unroll
            for (int nf = 0; nf < 4; nf++) {
                const float* base = Ws + (k0 + qa) * WS_STRIDE + wc * 32 + nf * 8 + g;
                bf[nf][0] = base[0];
                bf[nf][1] = base[4 * WS_STRIDE];
            }
#pragma unroll
            for (int mf = 0; mf < 4; mf++)
#pragma unroll
                for (int nf = 0; nf < 4; nf++) {
                    asm volatile(
                        "mma.sync.aligned.m16n8k8.row.col.f32.tf32.tf32.f32 "
                        "{%0,%1,%2,%3}, {%4,%5,%6,%7}, {%8,%9}, {%0,%1,%2,%3};"
                        : "+f"(acc[mf][nf][0]), "+f"(acc[mf][nf][1]),
                          "+f"(acc[mf][nf][2]), "+f"(acc[mf][nf][3])
                        : "r"(__float_as_uint(af[mf][0])), "r"(__float_as_uint(af[mf][1])),
                          "r"(__float_as_uint(af[mf][2])), "r"(__float_as_uint(af[mf][3])),
                          "r"(__float_as_uint(bf[nf][0])), "r"(__float_as_uint(bf[nf][1])));
                }
        }
        __syncthreads();
    }

    // ---- epilogue: global store + fused el/er ----
    float pel[8], per[8];
#pragma unroll
    for (int i = 0; i < 8; i++) { pel[i] = 0.f; per[i] = 0.f; }

#pragma unroll
    for (int mf = 0; mf < 4; mf++) {
        int r0 = row0 + wr * 64 + mf * 16 + g;
        int r1 = r0 + 8;
#pragma unroll
        for (int nf = 0; nf < 4; nf++) {
            int c = wc * 32 + nf * 8 + 2 * qa;
            float c0 = acc[mf][nf][0], c1 = acc[mf][nf][1];
            float c2 = acc[mf][nf][2], c3 = acc[mf][nf][3];
            float a0 = s_al[c], a1 = s_al[c + 1];
            float r0v = s_ar[c], r1v = s_ar[c + 1];
            pel[mf * 2 + 0] += c0 * a0 + c1 * a1;
            pel[mf * 2 + 1] += c2 * a0 + c3 * a1;
            per[mf * 2 + 0] += c0 * r0v + c1 * r1v;
            per[mf * 2 + 1] += c2 * r0v + c3 * r1v;
            if (r0 < M) *(float2*)(C + (size_t)r0 * 128 + c) = make_float2(c0, c1);
            if (r1 < M) *(float2*)(C + (size_t)r1 * 128 + c) = make_float2(c2, c3);
        }
    }
    // quad-reduce (lanes sharing g): shfl_xor 1, 2
#pragma unroll
    for (int i = 0; i < 8; i++) {
#pragma unroll
        for (int o = 1; o <= 2; o <<= 1) {
            pel[i] += __shfl_xor_sync(0xFFFFFFFFu, pel[i], o);
            per[i] += __shfl_xor_sync(0xFFFFFFFFu, per[i], o);
        }
    }
    // cross-warp reduce via smem (reuse As region; safe after the sync above)
    float* part_el = sm;        // [128][4]
    float* part_er = sm + 512;  // [128][4]
    __syncthreads();
    if (qa == 0) {
#pragma unroll
        for (int mf = 0; mf < 4; mf++) {
            int rl0 = wr * 64 + mf * 16 + g;
            part_el[rl0 * 4 + wc] = pel[mf * 2 + 0];
            part_el[(rl0 + 8) * 4 + wc] = pel[mf * 2 + 1];
            part_er[rl0 * 4 + wc] = per[mf * 2 + 0];
            part_er[(rl0 + 8) * 4 + wc] = per[mf * 2 + 1];
        }
    }
    __syncthreads();
    if (tid < 128 && row0 + tid < M) {
        float e = part_el[tid * 4] + part_el[tid * 4 + 1] + part_el[tid * 4 + 2] + part_el[tid * 4 + 3];
        float r = part_er[tid * 4] + part_er[tid * 4 + 1] + part_er[tid * 4 + 2] + part_er[tid * 4 + 3];
        g_el[row0 + tid] = e;
        g_er[row0 + tid] = r;
    }
}

// ---------------- warp-per-dst softmax + aggregation ----------------
__global__ void k_aggregate(const float* __restrict__ Wh, const float* __restrict__ bias,
                            float* __restrict__ hout) {
    int node = (blockIdx.x * blockDim.x + threadIdx.x) >> 5;
    int lane = threadIdx.x & 31;
    if (node >= NN) return;
    int start = g_rowptr[node];
    int end = g_rowptr[node + 1];
    float erd = g_er[node];

    float m = -INFINITY, s = 0.f;
    for (int base = start; base < end; base += 32) {
        int idx = base + lane;
        float e = -INFINITY;
        if (idx < end) {
            int sv = g_csrc[idx];
            e = lrelu(g_el[sv] + erd);
        }
        float cm = e;
#pragma unroll
        for (int o = 16; o > 0; o >>= 1) cm = fmaxf(cm, __shfl_xor_sync(0xFFFFFFFFu, cm, o));
        float nm = fmaxf(m, cm);
        float ex = __expf(e - nm);
#pragma unroll
        for (int o = 16; o > 0; o >>= 1) ex += __shfl_xor_sync(0xFFFFFFFFu, ex, o);
        float scale = (m == -INFINITY) ? 0.f : __expf(m - nm);
        s = s * scale + ex;
        m = nm;
    }
    float inv_s = (end > start) ? 1.f / s : 0.f;

    float4 acc = make_float4(0.f, 0.f, 0.f, 0.f);
    const float4* Wh4 = (const float4*)Wh;
    for (int idx = start; idx < end; idx++) {
        int sv = g_csrc[idx];
        float t = lrelu(g_el[sv] + erd);
        float a = __expf(t - m) * inv_s;
        float4 w = Wh4[(size_t)sv * 32 + lane];
        acc.x += a * w.x;
        acc.y += a * w.y;
        acc.z += a * w.z;
        acc.w += a * w.w;
    }
    float4 b4 = ((const float4*)bias)[lane];
    float4 o;
    o.x = eluf(acc.x + b4.x);
    o.y = eluf(acc.y + b4.y);
    o.z = eluf(acc.z + b4.z);
    o.w = eluf(acc.w + b4.w);
    ((float4*)hout)[(size_t)node * 32 + lane] = o;
}

// ---------------- graph pooling + classifier ----------------
__global__ void k_bounds(const int* __restrict__ gid) {
    int g = threadIdx.x;
    if (g > NG) return;
    int lo = 0, hi = NN;
    while (lo < hi) {
        int mid = (lo + hi) >> 1;
        if (gid[mid] < g) lo = mid + 1; else hi = mid;
    }
    g_gstart[g] = lo;
}

__global__ void k_pool(const float* __restrict__ h) {
    int g = blockIdx.x;
    int t = threadIdx.x;
    int st = g_gstart[g], en = g_gstart[g + 1];
    float s = 0.f;
    for (int i = st; i < en; i++) s += h[(size_t)i * DD + t];
    int c = en - st;
    g_hg[g * DD + t] = s / (float)max(c, 1);
}

__global__ void k_classify(const float* __restrict__ Wc, const float* __restrict__ bc,
                           float* __restrict__ out) {
    int t = threadIdx.x;
    if (t >= NG * NC) return;
    int g = t >> 1, c = t & 1;
    float s = 0.f;
#pragma unroll 4
    for (int k = 0; k < DD; k++) s += g_hg[g * DD + k] * Wc[k * NC + c];
    out[g * NC + c] = s + bc[c];
}

// ---------------- launch ----------------
extern "C" void kernel_launch(void* const* d_in, const int* in_sizes, int n_in,
                              void* d_out, int out_size) {
    const float* x = (const float*)d_in[0];
    const int* src = (const int*)d_in[1];
    const int* dst = (const int*)d_in[2];
    const int* gid = (const int*)d_in[3];
    const float* W[3]  = {(const float*)d_in[4],  (const float*)d_in[8],  (const float*)d_in[12]};
    const float* al[3] = {(const float*)d_in[5],  (const float*)d_in[9],  (const float*)d_in[13]};
    const float* ar[3] = {(const float*)d_in[6],  (const float*)d_in[10], (const float*)d_in[14]};
    const float* bb[3] = {(const float*)d_in[7],  (const float*)d_in[11], (const float*)d_in[15]};
    const float* Wc = (const float*)d_in[16];
    const float* bc = (const float*)d_in[17];
    float* out = (float*)d_out;

    float *pWh, *phA, *phB;
    int* pcnt;
    cudaGetSymbolAddress((void**)&pWh, g_Wh);
    cudaGetSymbolAddress((void**)&phA, g_hA);
    cudaGetSymbolAddress((void**)&phB, g_hB);
    cudaGetSymbolAddress((void**)&pcnt, g_cnt);

    static bool attr_set = false;
    if (!attr_set) {
        cudaFuncSetAttribute(k_gemm_mma, cudaFuncAttributeMaxDynamicSharedMemorySize,
                             SMEM_FLOATS * sizeof(float));
        attr_set = true;
    }

    // CSR build
    cudaMemsetAsync(pcnt, 0, NN * sizeof(int));
    k_hist<<<(NE + 255) / 256, 256>>>(dst);
    k_scan<<<1, 1024>>>();
    k_fillcsr<<<(NE + 255) / 256, 256>>>(src, dst);

    const int warpGrid = (NN * 32 + 255) / 256;
    const int gemmGrid = (NN + 127) / 128;
    const float* hin = x;
    float* bufs[2] = {phA, phB};
    for (int l = 0; l < 3; l++) {
        k_gemm_mma<<<gemmGrid, 256, SMEM_FLOATS * sizeof(float)>>>(hin, W[l], al[l], ar[l], pWh, NN);
        k_aggregate<<<warpGrid, 256>>>(pWh, bb[l], bufs[l & 1]);
        hin = bufs[l & 1];
    }

    k_bounds<<<1, 128>>>(gid);
    k_pool<<<NG, 128>>>(hin);
    k_classify<<<1, 128>>>(Wc, bc, out);
}

// round 5
// speedup vs baseline: 1.4969x; 1.1244x over previous
#include <cuda_runtime.h>
#include <math.h>
#include <stdint.h>

#define NN 50000
#define NE 800000
#define DD 128
#define NG 64
#define NC 2
#define SLOPE 0.2f
#define NBLK 196  // ceil(NN/256)

// ---------------- scratch (static device globals; no allocation) ----------------
__device__ float g_Wh[NN * DD];
__device__ float g_hA[NN * DD];
__device__ float g_hB[NN * DD];
__device__ float g_el[NN];
__device__ float g_er[NN];
__device__ int   g_rowptr[NN + 1];
__device__ int   g_fill[NN];
__device__ int   g_cnt[NN];
__device__ int   g_csrc[NE];
__device__ int   g_bsum[256];
__device__ float g_hg[NG * DD];
__device__ int   g_gstart[NG + 1];

// ---------------- helpers ----------------
__device__ __forceinline__ float eluf(float x) { return x > 0.f ? x : (__expf(x) - 1.f); }
__device__ __forceinline__ float lrelu(float x) { return x > 0.f ? x : SLOPE * x; }
__device__ __forceinline__ float totf32(float x) {
    uint32_t r;
    asm("cvt.rna.tf32.f32 %0, %1;" : "=r"(r) : "f"(x));
    return __uint_as_float(r);
}

// ---------------- CSR build ----------------
__global__ void k_hist4(const int4* __restrict__ dst4) {
    int i = blockIdx.x * blockDim.x + threadIdx.x;
    if (i < NE / 4) {
        int4 d = dst4[i];
        atomicAdd(&g_cnt[d.x], 1);
        atomicAdd(&g_cnt[d.y], 1);
        atomicAdd(&g_cnt[d.z], 1);
        atomicAdd(&g_cnt[d.w], 1);
    }
}

// two-level scan: block sums
__global__ void k_scan1() {
    int i = blockIdx.x * 256 + threadIdx.x;
    int c = (i < NN) ? g_cnt[i] : 0;
    int lane = threadIdx.x & 31, w = threadIdx.x >> 5;
#pragma unroll
    for (int o = 16; o > 0; o >>= 1) c += __shfl_xor_sync(0xFFFFFFFFu, c, o);
    __shared__ int ws[8];
    if (lane == 0) ws[w] = c;
    __syncthreads();
    if (threadIdx.x == 0) {
        int s = 0;
#pragma unroll
        for (int j = 0; j < 8; j++) s += ws[j];
        g_bsum[blockIdx.x] = s;
    }
}

// scan the 196 block sums (1 block, 256 threads)
__global__ void k_scan2() {
    int tid = threadIdx.x;
    int v = (tid < NBLK) ? g_bsum[tid] : 0;
    int lane = tid & 31, w = tid >> 5;
    int inc = v;
#pragma unroll
    for (int o = 1; o < 32; o <<= 1) {
        int t = __shfl_up_sync(0xFFFFFFFFu, inc, o);
        if (lane >= o) inc += t;
    }
    __shared__ int wt[8];
    if (lane == 31) wt[w] = inc;
    __syncthreads();
    if (tid == 0) {
        int run = 0;
#pragma unroll
        for (int j = 0; j < 8; j++) { int t = wt[j]; wt[j] = run; run += t; }
    }
    __syncthreads();
    int excl = inc - v + wt[w];
    if (tid < NBLK) g_bsum[tid] = excl;
    if (tid == 0) g_rowptr[NN] = NE;
}

// per-block exclusive scan + global offset -> rowptr, fill
__global__ void k_scan3() {
    int i = blockIdx.x * 256 + threadIdx.x;
    int c = (i < NN) ? g_cnt[i] : 0;
    int lane = threadIdx.x & 31, w = threadIdx.x >> 5;
    int inc = c;
#pragma unroll
    for (int o = 1; o < 32; o <<= 1) {
        int t = __shfl_up_sync(0xFFFFFFFFu, inc, o);
        if (lane >= o) inc += t;
    }
    __shared__ int wt[8];
    if (lane == 31) wt[w] = inc;
    __syncthreads();
    if (threadIdx.x == 0) {
        int run = 0;
#pragma unroll
        for (int j = 0; j < 8; j++) { int t = wt[j]; wt[j] = run; run += t; }
    }
    __syncthreads();
    int excl = inc - c + wt[w] + g_bsum[blockIdx.x];
    if (i < NN) {
        g_rowptr[i] = excl;
        g_fill[i] = excl;
    }
}

__global__ void k_fillcsr4(const int4* __restrict__ src4, const int4* __restrict__ dst4) {
    int i = blockIdx.x * blockDim.x + threadIdx.x;
    if (i < NE / 4) {
        int4 d = dst4[i];
        int4 s = src4[i];
        int p0 = atomicAdd(&g_fill[d.x], 1);
        int p1 = atomicAdd(&g_fill[d.y], 1);
        int p2 = atomicAdd(&g_fill[d.z], 1);
        int p3 = atomicAdd(&g_fill[d.w], 1);
        g_csrc[p0] = s.x;
        g_csrc[p1] = s.y;
        g_csrc[p2] = s.z;
        g_csrc[p3] = s.w;
    }
}

// ---------------- TF32 warp-MMA GEMM + fused el/er ----------------
#define AS_STRIDE 68
#define WS_STRIDE 136
#define SMEM_FLOATS (128 * AS_STRIDE + 64 * WS_STRIDE)

__global__ void __launch_bounds__(256, 2)
k_gemm_mma(const float* __restrict__ A, const float* __restrict__ W,
           const float* __restrict__ al, const float* __restrict__ ar,
           float* __restrict__ C, int M) {
    extern __shared__ float sm[];
    float* As = sm;                      // [128][AS_STRIDE]
    float* Ws = sm + 128 * AS_STRIDE;    // [64][WS_STRIDE]
    __shared__ float s_al[DD], s_ar[DD];

    int tid = threadIdx.x;
    int wid = tid >> 5, lane = tid & 31;
    int g = lane >> 2, qa = lane & 3;
    int wr = wid >> 2, wc = wid & 3;
    int row0 = blockIdx.x * 128;

    if (tid < 128) {
        s_al[tid] = al[tid];
        s_ar[tid] = ar[tid];
    }

    float acc[4][4][4];
#pragma unroll
    for (int i = 0; i < 4; i++)
#pragma unroll
        for (int j = 0; j < 4; j++)
#pragma unroll
            for (int k = 0; k < 4; k++) acc[i][j][k] = 0.f;

    for (int kc = 0; kc < 2; kc++) {
#pragma unroll
        for (int i = 0; i < 8; i++) {
            int idx = i * 256 + tid;
            int m = idx >> 4, kq = idx & 15;
            int gr = row0 + m;
            float4 v = make_float4(0.f, 0.f, 0.f, 0.f);
            if (gr < M) v = *(const float4*)(A + (size_t)gr * 128 + kc * 64 + kq * 4);
            float* p = As + m * AS_STRIDE + kq * 4;
            p[0] = totf32(v.x); p[1] = totf32(v.y); p[2] = totf32(v.z); p[3] = totf32(v.w);
        }
#pragma unroll
        for (int i = 0; i < 8; i++) {
            int idx = i * 256 + tid;
            int k = idx >> 5, nq = idx & 31;
            float4 v = *(const float4*)(W + (size_t)(kc * 64 + k) * 128 + nq * 4);
            float* p = Ws + k * WS_STRIDE + nq * 4;
            p[0] = totf32(v.x); p[1] = totf32(v.y); p[2] = totf32(v.z); p[3] = totf32(v.w);
        }
        __syncthreads();

#pragma unroll
        for (int ks = 0; ks < 8; ks++) {
            int k0 = ks * 8;
            float af[4][4];
#pragma unroll
            for (int mf = 0; mf < 4; mf++) {
                const float* base = As + (wr * 64 + mf * 16 + g) * AS_STRIDE + k0 + qa;
                af[mf][0] = base[0];
                af[mf][1] = base[8 * AS_STRIDE];
                af[mf][2] = base[4];
                af[mf][3] = base[8 * AS_STRIDE + 4];
            }
            float bf[4][2];
#pragma unroll
            for (int nf = 0; nf < 4; nf++) {
                const float* base = Ws + (k0 + qa) * WS_STRIDE + wc * 32 + nf * 8 + g;
                bf[nf][0] = base[0];
                bf[nf][1] = base[4 * WS_STRIDE];
            }
#pragma unroll
            for (int mf = 0; mf < 4; mf++)
#pragma unroll
                for (int nf = 0; nf < 4; nf++) {
                    asm volatile(
                        "mma.sync.aligned.m16n8k8.row.col.f32.tf32.tf32.f32 "
                        "{%0,%1,%2,%3}, {%4,%5,%6,%7}, {%8,%9}, {%0,%1,%2,%3};"
                        : "+f"(acc[mf][nf][0]), "+f"(acc[mf][nf][1]),
                          "+f"(acc[mf][nf][2]), "+f"(acc[mf][nf][3])
                        : "r"(__float_as_uint(af[mf][0])), "r"(__float_as_uint(af[mf][1])),
                          "r"(__float_as_uint(af[mf][2])), "r"(__float_as_uint(af[mf][3])),
                          "r"(__float_as_uint(bf[nf][0])), "r"(__float_as_uint(bf[nf][1])));
                }
        }
        __syncthreads();
    }

    float pel[8], per[8];
#pragma unroll
    for (int i = 0; i < 8; i++) { pel[i] = 0.f; per[i] = 0.f; }

#pragma unroll
    for (int mf = 0; mf < 4; mf++) {
        int r0 = row0 + wr * 64 + mf * 16 + g;
        int r1 = r0 + 8;
#pragma unroll
        for (int nf = 0; nf < 4; nf++) {
            int c = wc * 32 + nf * 8 + 2 * qa;
            float c0 = acc[mf][nf][0], c1 = acc[mf][nf][1];
            float c2 = acc[mf][nf][2], c3 = acc[mf][nf][3];
            float a0 = s_al[c], a1 = s_al[c + 1];
            float r0v = s_ar[c], r1v = s_ar[c + 1];
            pel[mf * 2 + 0] += c0 * a0 + c1 * a1;
            pel[mf * 2 + 1] += c2 * a0 + c3 * a1;
            per[mf * 2 + 0] += c0 * r0v + c1 * r1v;
            per[mf * 2 + 1] += c2 * r0v + c3 * r1v;
            if (r0 < M) *(float2*)(C + (size_t)r0 * 128 + c) = make_float2(c0, c1);
            if (r1 < M) *(float2*)(C + (size_t)r1 * 128 + c) = make_float2(c2, c3);
        }
    }
#pragma unroll
    for (int i = 0; i < 8; i++) {
#pragma unroll
        for (int o = 1; o <= 2; o <<= 1) {
            pel[i] += __shfl_xor_sync(0xFFFFFFFFu, pel[i], o);
            per[i] += __shfl_xor_sync(0xFFFFFFFFu, per[i], o);
        }
    }
    float* part_el = sm;
    float* part_er = sm + 512;
    __syncthreads();
    if (qa == 0) {
#pragma unroll
        for (int mf = 0; mf < 4; mf++) {
            int rl0 = wr * 64 + mf * 16 + g;
            part_el[rl0 * 4 + wc] = pel[mf * 2 + 0];
            part_el[(rl0 + 8) * 4 + wc] = pel[mf * 2 + 1];
            part_er[rl0 * 4 + wc] = per[mf * 2 + 0];
            part_er[(rl0 + 8) * 4 + wc] = per[mf * 2 + 1];
        }
    }
    __syncthreads();
    if (tid < 128 && row0 + tid < M) {
        float e = part_el[tid * 4] + part_el[tid * 4 + 1] + part_el[tid * 4 + 2] + part_el[tid * 4 + 3];
        float r = part_er[tid * 4] + part_er[tid * 4 + 1] + part_er[tid * 4 + 2] + part_er[tid * 4 + 3];
        g_el[row0 + tid] = e;
        g_er[row0 + tid] = r;
    }
}

// ---------------- warp-per-dst softmax + aggregation (MLP-4 gather) ----------------
__global__ void __launch_bounds__(256)
k_aggregate(const float* __restrict__ Wh, const float* __restrict__ bias,
            float* __restrict__ hout) {
    __shared__ float se[8][64];  // cached edge scores per warp
    int w = threadIdx.x >> 5;
    int lane = threadIdx.x & 31;
    int node = (blockIdx.x * blockDim.x + threadIdx.x) >> 5;
    if (node >= NN) return;
    int start = g_rowptr[node];
    int deg = g_rowptr[node + 1] - start;
    float erd = g_er[node];

    // phase 1: online softmax stats; cache e for i<64
    float m = -INFINITY, s = 0.f;
    for (int base = 0; base < deg; base += 32) {
        int i = base + lane;
        float e = -INFINITY;
        if (i < deg) {
            int sv = g_csrc[start + i];
            e = lrelu(g_el[sv] + erd);
            if (i < 64) se[w][i] = e;
        }
        float cm = e;
#pragma unroll
        for (int o = 16; o > 0; o >>= 1) cm = fmaxf(cm, __shfl_xor_sync(0xFFFFFFFFu, cm, o));
        float nm = fmaxf(m, cm);
        float ex = __expf(e - nm);
#pragma unroll
        for (int o = 16; o > 0; o >>= 1) ex += __shfl_xor_sync(0xFFFFFFFFu, ex, o);
        float scale = (m == -INFINITY) ? 0.f : __expf(m - nm);
        s = s * scale + ex;
        m = nm;
    }
    __syncwarp();
    float inv_s = (deg > 0) ? 1.f / s : 0.f;
    bool cached = (deg <= 64);

    // phase 2: unroll-by-4 row gather
    float4 acc = make_float4(0.f, 0.f, 0.f, 0.f);
    const float4* Wh4 = (const float4*)Wh;
    int i = 0;
    for (; i + 4 <= deg; i += 4) {
        int sv0 = g_csrc[start + i + 0];
        int sv1 = g_csrc[start + i + 1];
        int sv2 = g_csrc[start + i + 2];
        int sv3 = g_csrc[start + i + 3];
        float e0 = cached ? se[w][i + 0] : lrelu(g_el[sv0] + erd);
        float e1 = cached ? se[w][i + 1] : lrelu(g_el[sv1] + erd);
        float e2 = cached ? se[w][i + 2] : lrelu(g_el[sv2] + erd);
        float e3 = cached ? se[w][i + 3] : lrelu(g_el[sv3] + erd);
        float a0 = __expf(e0 - m) * inv_s;
        float a1 = __expf(e1 - m) * inv_s;
        float a2 = __expf(e2 - m) * inv_s;
        float a3 = __expf(e3 - m) * inv_s;
        float4 w0 = Wh4[(size_t)sv0 * 32 + lane];
        float4 w1 = Wh4[(size_t)sv1 * 32 + lane];
        float4 w2 = Wh4[(size_t)sv2 * 32 + lane];
        float4 w3 = Wh4[(size_t)sv3 * 32 + lane];
        acc.x += a0 * w0.x + a1 * w1.x + a2 * w2.x + a3 * w3.x;
        acc.y += a0 * w0.y + a1 * w1.y + a2 * w2.y + a3 * w3.y;
        acc.z += a0 * w0.z + a1 * w1.z + a2 * w2.z + a3 * w3.z;
        acc.w += a0 * w0.w + a1 * w1.w + a2 * w2.w + a3 * w3.w;
    }
    for (; i < deg; i++) {
        int sv = g_csrc[start + i];
        float e = cached ? se[w][i] : lrelu(g_el[sv] + erd);
        float a = __expf(e - m) * inv_s;
        float4 wv = Wh4[(size_t)sv * 32 + lane];
        acc.x += a * wv.x;
        acc.y += a * wv.y;
        acc.z += a * wv.z;
        acc.w += a * wv.w;
    }
    float4 b4 = ((const float4*)bias)[lane];
    float4 o;
    o.x = eluf(acc.x + b4.x);
    o.y = eluf(acc.y + b4.y);
    o.z = eluf(acc.z + b4.z);
    o.w = eluf(acc.w + b4.w);
    ((float4*)hout)[(size_t)node * 32 + lane] = o;
}

// ---------------- graph pooling + classifier ----------------
__global__ void k_bounds(const int* __restrict__ gid) {
    int g = threadIdx.x;
    if (g > NG) return;
    int lo = 0, hi = NN;
    while (lo < hi) {
        int mid = (lo + hi) >> 1;
        if (gid[mid] < g) lo = mid + 1; else hi = mid;
    }
    g_gstart[g] = lo;
}

__global__ void k_pool(const float* __restrict__ h) {
    int g = blockIdx.x;
    int t = threadIdx.x;
    int st = g_gstart[g], en = g_gstart[g + 1];
    float s0 = 0.f, s1 = 0.f, s2 = 0.f, s3 = 0.f;
    int i = st;
    for (; i + 4 <= en; i += 4) {
        s0 += h[(size_t)(i + 0) * DD + t];
        s1 += h[(size_t)(i + 1) * DD + t];
        s2 += h[(size_t)(i + 2) * DD + t];
        s3 += h[(size_t)(i + 3) * DD + t];
    }
    for (; i < en; i++) s0 += h[(size_t)i * DD + t];
    float s = (s0 + s1) + (s2 + s3);
    int c = en - st;
    g_hg[g * DD + t] = s / (float)max(c, 1);
}

__global__ void k_classify(const float* __restrict__ Wc, const float* __restrict__ bc,
                           float* __restrict__ out) {
    int t = threadIdx.x;
    if (t >= NG * NC) return;
    int g = t >> 1, c = t & 1;
    float s = 0.f;
#pragma unroll 4
    for (int k = 0; k < DD; k++) s += g_hg[g * DD + k] * Wc[k * NC + c];
    out[g * NC + c] = s + bc[c];
}

// ---------------- launch ----------------
extern "C" void kernel_launch(void* const* d_in, const int* in_sizes, int n_in,
                              void* d_out, int out_size) {
    const float* x = (const float*)d_in[0];
    const int* src = (const int*)d_in[1];
    const int* dst = (const int*)d_in[2];
    const int* gid = (const int*)d_in[3];
    const float* W[3]  = {(const float*)d_in[4],  (const float*)d_in[8],  (const float*)d_in[12]};
    const float* al[3] = {(const float*)d_in[5],  (const float*)d_in[9],  (const float*)d_in[13]};
    const float* ar[3] = {(const float*)d_in[6],  (const float*)d_in[10], (const float*)d_in[14]};
    const float* bb[3] = {(const float*)d_in[7],  (const float*)d_in[11], (const float*)d_in[15]};
    const float* Wc = (const float*)d_in[16];
    const float* bc = (const float*)d_in[17];
    float* out = (float*)d_out;

    float *pWh, *phA, *phB;
    int* pcnt;
    cudaGetSymbolAddress((void**)&pWh, g_Wh);
    cudaGetSymbolAddress((void**)&phA, g_hA);
    cudaGetSymbolAddress((void**)&phB, g_hB);
    cudaGetSymbolAddress((void**)&pcnt, g_cnt);

    static bool attr_set = false;
    if (!attr_set) {
        cudaFuncSetAttribute(k_gemm_mma, cudaFuncAttributeMaxDynamicSharedMemorySize,
                             SMEM_FLOATS * sizeof(float));
        attr_set = true;
    }

    // CSR build
    cudaMemsetAsync(pcnt, 0, NN * sizeof(int));
    const int eg4 = (NE / 4 + 255) / 256;
    k_hist4<<<eg4, 256>>>((const int4*)dst);
    k_scan1<<<NBLK, 256>>>();
    k_scan2<<<1, 256>>>();
    k_scan3<<<NBLK, 256>>>();
    k_fillcsr4<<<eg4, 256>>>((const int4*)src, (const int4*)dst);

    const int warpGrid = (NN * 32 + 255) / 256;
    const int gemmGrid = (NN + 127) / 128;
    const float* hin = x;
    float* bufs[2] = {phA, phB};
    for (int l = 0; l < 3; l++) {
        k_gemm_mma<<<gemmGrid, 256, SMEM_FLOATS * sizeof(float)>>>(hin, W[l], al[l], ar[l], pWh, NN);
        k_aggregate<<<warpGrid, 256>>>(pWh, bb[l], bufs[l & 1]);
        hin = bufs[l & 1];
    }

    k_bounds<<<1, 128>>>(gid);
    k_pool<<<NG, 128>>>(hin);
    k_classify<<<1, 128>>>(Wc, bc, out);
}

// round 8
// speedup vs baseline: 1.5435x; 1.0311x over previous
#include <cuda_runtime.h>
#include <math.h>
#include <stdint.h>

#define NN 50000
#define NE 800000
#define DD 128
#define NG 64
#define NC 2
#define SLOPE 0.2f
#define NBLK 196  // ceil(NN/256)

// ---------------- scratch (static device globals; no allocation) ----------------
__device__ float g_Wh[NN * DD];
__device__ float g_hA[NN * DD];
__device__ float g_hB[NN * DD];
__device__ float g_el[NN];
__device__ float g_er[NN];
__device__ int   g_rowptr[NN + 1];
__device__ int   g_fill[NN];
__device__ int   g_cnt[NN];
__device__ int   g_csrc[NE];
__device__ int   g_bsum[256];
__device__ float g_hg[NG * DD];
__device__ int   g_gstart[NG + 1];

// ---------------- helpers ----------------
__device__ __forceinline__ float eluf(float x) { return x > 0.f ? x : (__expf(x) - 1.f); }
__device__ __forceinline__ float lrelu(float x) { return x > 0.f ? x : SLOPE * x; }
__device__ __forceinline__ float totf32(float x) {
    uint32_t r;
    asm("cvt.rna.tf32.f32 %0, %1;" : "=r"(r) : "f"(x));
    return __uint_as_float(r);
}
__device__ __forceinline__ void cp16(uint32_t dst_smem, const void* src, bool valid) {
    asm volatile("cp.async.ca.shared.global [%0], [%1], 16, %2;"
                 :: "r"(dst_smem), "l"(src), "r"(valid ? 16 : 0));
}

// ---------------- CSR build ----------------
__global__ void k_hist4(const int4* __restrict__ dst4) {
    int i = blockIdx.x * blockDim.x + threadIdx.x;
    if (i < NE / 4) {
        int4 d = dst4[i];
        atomicAdd(&g_cnt[d.x], 1);
        atomicAdd(&g_cnt[d.y], 1);
        atomicAdd(&g_cnt[d.z], 1);
        atomicAdd(&g_cnt[d.w], 1);
    }
}

__global__ void k_scan1() {
    int i = blockIdx.x * 256 + threadIdx.x;
    int c = (i < NN) ? g_cnt[i] : 0;
    int lane = threadIdx.x & 31, w = threadIdx.x >> 5;
#pragma unroll
    for (int o = 16; o > 0; o >>= 1) c += __shfl_xor_sync(0xFFFFFFFFu, c, o);
    __shared__ int ws[8];
    if (lane == 0) ws[w] = c;
    __syncthreads();
    if (threadIdx.x == 0) {
        int s = 0;
#pragma unroll
        for (int j = 0; j < 8; j++) s += ws[j];
        g_bsum[blockIdx.x] = s;
    }
}

__global__ void k_scan2() {
    int tid = threadIdx.x;
    int v = (tid < NBLK) ? g_bsum[tid] : 0;
    int lane = tid & 31, w = tid >> 5;
    int inc = v;
#pragma unroll
    for (int o = 1; o < 32; o <<= 1) {
        int t = __shfl_up_sync(0xFFFFFFFFu, inc, o);
        if (lane >= o) inc += t;
    }
    __shared__ int wt[8];
    if (lane == 31) wt[w] = inc;
    __syncthreads();
    if (tid == 0) {
        int run = 0;
#pragma unroll
        for (int j = 0; j < 8; j++) { int t = wt[j]; wt[j] = run; run += t; }
    }
    __syncthreads();
    int excl = inc - v + wt[w];
    if (tid < NBLK) g_bsum[tid] = excl;
    if (tid == 0) g_rowptr[NN] = NE;
}

__global__ void k_scan3() {
    int i = blockIdx.x * 256 + threadIdx.x;
    int c = (i < NN) ? g_cnt[i] : 0;
    int lane = threadIdx.x & 31, w = threadIdx.x >> 5;
    int inc = c;
#pragma unroll
    for (int o = 1; o < 32; o <<= 1) {
        int t = __shfl_up_sync(0xFFFFFFFFu, inc, o);
        if (lane >= o) inc += t;
    }
    __shared__ int wt[8];
    if (lane == 31) wt[w] = inc;
    __syncthreads();
    if (threadIdx.x == 0) {
        int run = 0;
#pragma unroll
        for (int j = 0; j < 8; j++) { int t = wt[j]; wt[j] = run; run += t; }
    }
    __syncthreads();
    int excl = inc - c + wt[w] + g_bsum[blockIdx.x];
    if (i < NN) {
        g_rowptr[i] = excl;
        g_fill[i] = excl;
    }
}

__global__ void k_fillcsr4(const int4* __restrict__ src4, const int4* __restrict__ dst4) {
    int i = blockIdx.x * blockDim.x + threadIdx.x;
    if (i < NE / 4) {
        int4 d = dst4[i];
        int4 s = src4[i];
        int p0 = atomicAdd(&g_fill[d.x], 1);
        int p1 = atomicAdd(&g_fill[d.y], 1);
        int p2 = atomicAdd(&g_fill[d.z], 1);
        int p3 = atomicAdd(&g_fill[d.w], 1);
        g_csrc[p0] = s.x;
        g_csrc[p1] = s.y;
        g_csrc[p2] = s.z;
        g_csrc[p3] = s.w;
    }
}

// ---------------- TF32 warp-MMA GEMM, cp.async double-buffered + fused el/er ----------------
// K split into 4 chunks of 32. As[2][128][36], Ws[2][32][136].
#define AS_CH 36
#define WS_CH 136
#define CHA (128 * AS_CH)   // floats per A chunk buffer (4608)
#define CHW (32 * WS_CH)    // floats per W chunk buffer (4352)
#define SMEM_FLOATS (2 * CHA + 2 * CHW)

__global__ void __launch_bounds__(256, 2)
k_gemm_mma(const float* __restrict__ A, const float* __restrict__ W,
           const float* __restrict__ al, const float* __restrict__ ar,
           float* __restrict__ C, int M) {
    extern __shared__ float sm[];
    float* AsB[2] = {sm, sm + CHA};
    float* WsB[2] = {sm + 2 * CHA, sm + 2 * CHA + CHW};
    __shared__ float s_al[DD], s_ar[DD];

    int tid = threadIdx.x;
    int wid = tid >> 5, lane = tid & 31;
    int g = lane >> 2, qa = lane & 3;
    int wr = wid >> 2, wc = wid & 3;
    int row0 = blockIdx.x * 128;

    if (tid < 128) {
        s_al[tid] = al[tid];
        s_ar[tid] = ar[tid];
    }

    uint32_t sAs[2], sWs[2];
#pragma unroll
    for (int b = 0; b < 2; b++) {
        sAs[b] = (uint32_t)__cvta_generic_to_shared(AsB[b]);
        sWs[b] = (uint32_t)__cvta_generic_to_shared(WsB[b]);
    }

    // per-thread load coordinates (4 float4 each for A and W per chunk)
    int am[4], af4[4], wk[4], wf4[4];
    bool avalid[4];
#pragma unroll
    for (int i = 0; i < 4; i++) {
        int idx = i * 256 + tid;
        am[i] = idx >> 3;  af4[i] = idx & 7;
        wk[i] = idx >> 5;  wf4[i] = idx & 31;
        avalid[i] = (row0 + am[i]) < M;
    }

    auto prefetch = [&](int c, int b) {
#pragma unroll
        for (int i = 0; i < 4; i++) {
            cp16(sAs[b] + (uint32_t)(am[i] * AS_CH + af4[i] * 4) * 4,
                 A + (size_t)(row0 + am[i]) * 128 + c * 32 + af4[i] * 4, avalid[i]);
            cp16(sWs[b] + (uint32_t)(wk[i] * WS_CH + wf4[i] * 4) * 4,
                 W + (size_t)(c * 32 + wk[i]) * 128 + wf4[i] * 4, true);
        }
        asm volatile("cp.async.commit_group;");
    };

    float acc[4][4][4];
#pragma unroll
    for (int i = 0; i < 4; i++)
#pragma unroll
        for (int j = 0; j < 4; j++)
#pragma unroll
            for (int k = 0; k < 4; k++) acc[i][j][k] = 0.f;

    prefetch(0, 0);
#pragma unroll
    for (int c = 0; c < 4; c++) {
        if (c < 3) prefetch(c + 1, (c + 1) & 1);
        if (c < 3) asm volatile("cp.async.wait_group 1;");
        else       asm volatile("cp.async.wait_group 0;");
        __syncthreads();
        const float* As = AsB[c & 1];
        const float* Ws = WsB[c & 1];
#pragma unroll
        for (int ks = 0; ks < 4; ks++) {
            int k0 = ks * 8;
            float af[4][4];
#pragma unroll
            for (int mf = 0; mf < 4; mf++) {
                const float* base = As + (wr * 64 + mf * 16 + g) * AS_CH + k0 + qa;
                af[mf][0] = totf32(base[0]);
                af[mf][1] = totf32(base[8 * AS_CH]);
                af[mf][2] = totf32(base[4]);
                af[mf][3] = totf32(base[8 * AS_CH + 4]);
            }
            float bf[4][2];
#pragma unroll
            for (int nf = 0; nf < 4; nf++) {
                const float* base = Ws + (k0 + qa) * WS_CH + wc * 32 + nf * 8 + g;
                bf[nf][0] = totf32(base[0]);
                bf[nf][1] = totf32(base[4 * WS_CH]);
            }
#pragma unroll
            for (int mf = 0; mf < 4; mf++)
#pragma unroll
                for (int nf = 0; nf < 4; nf++) {
                    asm volatile(
                        "mma.sync.aligned.m16n8k8.row.col.f32.tf32.tf32.f32 "
                        "{%0,%1,%2,%3}, {%4,%5,%6,%7}, {%8,%9}, {%0,%1,%2,%3};"
                        : "+f"(acc[mf][nf][0]), "+f"(acc[mf][nf][1]),
                          "+f"(acc[mf][nf][2]), "+f"(acc[mf][nf][3])
                        : "r"(__float_as_uint(af[mf][0])), "r"(__float_as_uint(af[mf][1])),
                          "r"(__float_as_uint(af[mf][2])), "r"(__float_as_uint(af[mf][3])),
                          "r"(__float_as_uint(bf[nf][0])), "r"(__float_as_uint(bf[nf][1])));
                }
        }
        __syncthreads();
    }

    // ---- epilogue: global store + fused el/er ----
    float pel[8], per[8];
#pragma unroll
    for (int i = 0; i < 8; i++) { pel[i] = 0.f; per[i] = 0.f; }

#pragma unroll
    for (int mf = 0; mf < 4; mf++) {
        int r0 = row0 + wr * 64 + mf * 16 + g;
        int r1 = r0 + 8;
#pragma unroll
        for (int nf = 0; nf < 4; nf++) {
            int c = wc * 32 + nf * 8 + 2 * qa;
            float c0 = acc[mf][nf][0], c1 = acc[mf][nf][1];
            float c2 = acc[mf][nf][2], c3 = acc[mf][nf][3];
            float a0 = s_al[c], a1 = s_al[c + 1];
            float r0v = s_ar[c], r1v = s_ar[c + 1];
            pel[mf * 2 + 0] += c0 * a0 + c1 * a1;
            pel[mf * 2 + 1] += c2 * a0 + c3 * a1;
            per[mf * 2 + 0] += c0 * r0v + c1 * r1v;
            per[mf * 2 + 1] += c2 * r0v + c3 * r1v;
            if (r0 < M) *(float2*)(C + (size_t)r0 * 128 + c) = make_float2(c0, c1);
            if (r1 < M) *(float2*)(C + (size_t)r1 * 128 + c) = make_float2(c2, c3);
        }
    }
#pragma unroll
    for (int i = 0; i < 8; i++) {
#pragma unroll
        for (int o = 1; o <= 2; o <<= 1) {
            pel[i] += __shfl_xor_sync(0xFFFFFFFFu, pel[i], o);
            per[i] += __shfl_xor_sync(0xFFFFFFFFu, per[i], o);
        }
    }
    float* part_el = sm;
    float* part_er = sm + 512;
    __syncthreads();
    if (qa == 0) {
#pragma unroll
        for (int mf = 0; mf < 4; mf++) {
            int rl0 = wr * 64 + mf * 16 + g;
            part_el[rl0 * 4 + wc] = pel[mf * 2 + 0];
            part_el[(rl0 + 8) * 4 + wc] = pel[mf * 2 + 1];
            part_er[rl0 * 4 + wc] = per[mf * 2 + 0];
            part_er[(rl0 + 8) * 4 + wc] = per[mf * 2 + 1];
        }
    }
    __syncthreads();
    if (tid < 128 && row0 + tid < M) {
        float e = part_el[tid * 4] + part_el[tid * 4 + 1] + part_el[tid * 4 + 2] + part_el[tid * 4 + 3];
        float r = part_er[tid * 4] + part_er[tid * 4 + 1] + part_er[tid * 4 + 2] + part_er[tid * 4 + 3];
        g_el[row0 + tid] = e;
        g_er[row0 + tid] = r;
    }
}

// ---------------- warp-per-dst softmax + aggregation (MLP-4 gather) ----------------
__global__ void __launch_bounds__(256)
k_aggregate(const float* __restrict__ Wh, const float* __restrict__ bias,
            float* __restrict__ hout) {
    __shared__ float se[8][64];
    int w = threadIdx.x >> 5;
    int lane = threadIdx.x & 31;
    int node = (blockIdx.x * blockDim.x + threadIdx.x) >> 5;
    if (node >= NN) return;
    int start = g_rowptr[node];
    int deg = g_rowptr[node + 1] - start;
    float erd = g_er[node];

    float m = -INFINITY, s = 0.f;
    for (int base = 0; base < deg; base += 32) {
        int i = base + lane;
        float e = -INFINITY;
        if (i < deg) {
            int sv = g_csrc[start + i];
            e = lrelu(g_el[sv] + erd);
            if (i < 64) se[w][i] = e;
        }
        float cm = e;
#pragma unroll
        for (int o = 16; o > 0; o >>= 1) cm = fmaxf(cm, __shfl_xor_sync(0xFFFFFFFFu, cm, o));
        float nm = fmaxf(m, cm);
        float ex = __expf(e - nm);
#pragma unroll
        for (int o = 16; o > 0; o >>= 1) ex += __shfl_xor_sync(0xFFFFFFFFu, ex, o);
        float scale = (m == -INFINITY) ? 0.f : __expf(m - nm);
        s = s * scale + ex;
        m = nm;
    }
    __syncwarp();
    float inv_s = (deg > 0) ? 1.f / s : 0.f;
    bool cached = (deg <= 64);

    float4 acc = make_float4(0.f, 0.f, 0.f, 0.f);
    const float4* Wh4 = (const float4*)Wh;
    int i = 0;
    for (; i + 4 <= deg; i += 4) {
        int sv0 = g_csrc[start + i + 0];
        int sv1 = g_csrc[start + i + 1];
        int sv2 = g_csrc[start + i + 2];
        int sv3 = g_csrc[start + i + 3];
        float e0 = cached ? se[w][i + 0] : lrelu(g_el[sv0] + erd);
        float e1 = cached ? se[w][i + 1] : lrelu(g_el[sv1] + erd);
        float e2 = cached ? se[w][i + 2] : lrelu(g_el[sv2] + erd);
        float e3 = cached ? se[w][i + 3] : lrelu(g_el[sv3] + erd);
        float a0 = __expf(e0 - m) * inv_s;
        float a1 = __expf(e1 - m) * inv_s;
        float a2 = __expf(e2 - m) * inv_s;
        float a3 = __expf(e3 - m) * inv_s;
        float4 w0 = Wh4[(size_t)sv0 * 32 + lane];
        float4 w1 = Wh4[(size_t)sv1 * 32 + lane];
        float4 w2 = Wh4[(size_t)sv2 * 32 + lane];
        float4 w3 = Wh4[(size_t)sv3 * 32 + lane];
        acc.x += a0 * w0.x + a1 * w1.x + a2 * w2.x + a3 * w3.x;
        acc.y += a0 * w0.y + a1 * w1.y + a2 * w2.y + a3 * w3.y;
        acc.z += a0 * w0.z + a1 * w1.z + a2 * w2.z + a3 * w3.z;
        acc.w += a0 * w0.w + a1 * w1.w + a2 * w2.w + a3 * w3.w;
    }
    for (; i < deg; i++) {
        int sv = g_csrc[start + i];
        float e = cached ? se[w][i] : lrelu(g_el[sv] + erd);
        float a = __expf(e - m) * inv_s;
        float4 wv = Wh4[(size_t)sv * 32 + lane];
        acc.x += a * wv.x;
        acc.y += a * wv.y;
        acc.z += a * wv.z;
        acc.w += a * wv.w;
    }
    float4 b4 = ((const float4*)bias)[lane];
    float4 o;
    o.x = eluf(acc.x + b4.x);
    o.y = eluf(acc.y + b4.y);
    o.z = eluf(acc.z + b4.z);
    o.w = eluf(acc.w + b4.w);
    ((float4*)hout)[(size_t)node * 32 + lane] = o;
}

// ---------------- graph pooling + classifier ----------------
__global__ void k_bounds(const int* __restrict__ gid) {
    int g = threadIdx.x;
    if (g > NG) return;
    int lo = 0, hi = NN;
    while (lo < hi) {
        int mid = (lo + hi) >> 1;
        if (gid[mid] < g) lo = mid + 1; else hi = mid;
    }
    g_gstart[g] = lo;
}

__global__ void k_pool(const float* __restrict__ h) {
    int g = blockIdx.x;
    int t = threadIdx.x;
    int st = g_gstart[g], en = g_gstart[g + 1];
    float s0 = 0.f, s1 = 0.f, s2 = 0.f, s3 = 0.f;
    int i = st;
    for (; i + 4 <= en; i += 4) {
        s0 += h[(size_t)(i + 0) * DD + t];
        s1 += h[(size_t)(i + 1) * DD + t];
        s2 += h[(size_t)(i + 2) * DD + t];
        s3 += h[(size_t)(i + 3) * DD + t];
    }
    for (; i < en; i++) s0 += h[(size_t)i * DD + t];
    float s = (s0 + s1) + (s2 + s3);
    int c = en - st;
    g_hg[g * DD + t] = s / (float)max(c, 1);
}

__global__ void k_classify(const float* __restrict__ Wc, const float* __restrict__ bc,
                           float* __restrict__ out) {
    int t = threadIdx.x;
    if (t >= NG * NC) return;
    int g = t >> 1, c = t & 1;
    float s = 0.f;
#pragma unroll 4
    for (int k = 0; k < DD; k++) s += g_hg[g * DD + k] * Wc[k * NC + c];
    out[g * NC + c] = s + bc[c];
}

// ---------------- launch (single stream; no stream/event creation) ----------------
extern "C" void kernel_launch(void* const* d_in, const int* in_sizes, int n_in,
                              void* d_out, int out_size) {
    const float* x = (const float*)d_in[0];
    const int* src = (const int*)d_in[1];
    const int* dst = (const int*)d_in[2];
    const int* gid = (const int*)d_in[3];
    const float* W[3]  = {(const float*)d_in[4],  (const float*)d_in[8],  (const float*)d_in[12]};
    const float* al[3] = {(const float*)d_in[5],  (const float*)d_in[9],  (const float*)d_in[13]};
    const float* ar[3] = {(const float*)d_in[6],  (const float*)d_in[10], (const float*)d_in[14]};
    const float* bb[3] = {(const float*)d_in[7],  (const float*)d_in[11], (const float*)d_in[15]};
    const float* Wc = (const float*)d_in[16];
    const float* bc = (const float*)d_in[17];
    float* out = (float*)d_out;

    float *pWh, *phA, *phB;
    int* pcnt;
    cudaGetSymbolAddress((void**)&pWh, g_Wh);
    cudaGetSymbolAddress((void**)&phA, g_hA);
    cudaGetSymbolAddress((void**)&phB, g_hB);
    cudaGetSymbolAddress((void**)&pcnt, g_cnt);

    static bool attr_set = false;
    if (!attr_set) {
        cudaFuncSetAttribute(k_gemm_mma, cudaFuncAttributeMaxDynamicSharedMemorySize,
                             SMEM_FLOATS * sizeof(float));
        attr_set = true;
    }

    // CSR build
    cudaMemsetAsync(pcnt, 0, NN * sizeof(int));
    const int eg4 = (NE / 4 + 255) / 256;
    k_hist4<<<eg4, 256>>>((const int4*)dst);
    k_scan1<<<NBLK, 256>>>();
    k_scan2<<<1, 256>>>();
    k_scan3<<<NBLK, 256>>>();
    k_fillcsr4<<<eg4, 256>>>((const int4*)src, (const int4*)dst);

    const int warpGrid = (NN * 32 + 255) / 256;
    const int gemmGrid = (NN + 127) / 128;
    const float* hin = x;
    float* bufs[2] = {phA, phB};
    for (int l = 0; l < 3; l++) {
        k_gemm_mma<<<gemmGrid, 256, SMEM_FLOATS * sizeof(float)>>>(hin, W[l], al[l], ar[l], pWh, NN);
        k_aggregate<<<warpGrid, 256>>>(pWh, bb[l], bufs[l & 1]);
        hin = bufs[l & 1];
    }

    k_bounds<<<1, 128>>>(gid);
    k_pool<<<NG, 128>>>(hin);
    k_classify<<<1, 128>>>(Wc, bc, out);
}

// round 9
// speedup vs baseline: 1.5709x; 1.0177x over previous
#include <cuda_runtime.h>
#include <math.h>
#include <stdint.h>

#define NN 50000
#define NE 800000
#define DD 128
#define NG 64
#define NC 2
#define SLOPE 0.2f
#define NBLK 196  // ceil(NN/256)

// ---------------- scratch (static device globals; no allocation) ----------------
__device__ float g_Wh[NN * DD];
__device__ float g_hA[NN * DD];
__device__ float g_hB[NN * DD];
__device__ float g_el[NN];
__device__ float g_er[NN];
__device__ int   g_rowptr[NN + 1];
__device__ int   g_fill[NN];
__device__ int   g_cnt[NN];
__device__ int   g_csrc[NE];
__device__ int   g_bsum[256];
__device__ float g_hg[NG * DD];
__device__ int   g_gstart[NG + 1];

// ---------------- helpers ----------------
__device__ __forceinline__ float eluf(float x) { return x > 0.f ? x : (__expf(x) - 1.f); }
__device__ __forceinline__ float lrelu(float x) { return x > 0.f ? x : SLOPE * x; }
__device__ __forceinline__ float totf32(float x) {
    uint32_t r;
    asm("cvt.rna.tf32.f32 %0, %1;" : "=r"(r) : "f"(x));
    return __uint_as_float(r);
}
__device__ __forceinline__ void cp16(uint32_t dst_smem, const void* src, bool valid) {
    asm volatile("cp.async.ca.shared.global [%0], [%1], 16, %2;"
                 :: "r"(dst_smem), "l"(src), "r"(valid ? 16 : 0));
}

// ---------------- CSR build ----------------
__global__ void k_hist4(const int4* __restrict__ dst4) {
    int i = blockIdx.x * blockDim.x + threadIdx.x;
    if (i < NE / 4) {
        int4 d = dst4[i];
        atomicAdd(&g_cnt[d.x], 1);
        atomicAdd(&g_cnt[d.y], 1);
        atomicAdd(&g_cnt[d.z], 1);
        atomicAdd(&g_cnt[d.w], 1);
    }
}

__global__ void k_scan1() {
    int i = blockIdx.x * 256 + threadIdx.x;
    int c = (i < NN) ? g_cnt[i] : 0;
    int lane = threadIdx.x & 31, w = threadIdx.x >> 5;
#pragma unroll
    for (int o = 16; o > 0; o >>= 1) c += __shfl_xor_sync(0xFFFFFFFFu, c, o);
    __shared__ int ws[8];
    if (lane == 0) ws[w] = c;
    __syncthreads();
    if (threadIdx.x == 0) {
        int s = 0;
#pragma unroll
        for (int j = 0; j < 8; j++) s += ws[j];
        g_bsum[blockIdx.x] = s;
    }
}

__global__ void k_scan2() {
    int tid = threadIdx.x;
    int v = (tid < NBLK) ? g_bsum[tid] : 0;
    int lane = tid & 31, w = tid >> 5;
    int inc = v;
#pragma unroll
    for (int o = 1; o < 32; o <<= 1) {
        int t = __shfl_up_sync(0xFFFFFFFFu, inc, o);
        if (lane >= o) inc += t;
    }
    __shared__ int wt[8];
    if (lane == 31) wt[w] = inc;
    __syncthreads();
    if (tid == 0) {
        int run = 0;
#pragma unroll
        for (int j = 0; j < 8; j++) { int t = wt[j]; wt[j] = run; run += t; }
    }
    __syncthreads();
    int excl = inc - v + wt[w];
    if (tid < NBLK) g_bsum[tid] = excl;
    if (tid == 0) g_rowptr[NN] = NE;
}

__global__ void k_scan3() {
    int i = blockIdx.x * 256 + threadIdx.x;
    int c = (i < NN) ? g_cnt[i] : 0;
    int lane = threadIdx.x & 31, w = threadIdx.x >> 5;
    int inc = c;
#pragma unroll
    for (int o = 1; o < 32; o <<= 1) {
        int t = __shfl_up_sync(0xFFFFFFFFu, inc, o);
        if (lane >= o) inc += t;
    }
    __shared__ int wt[8];
    if (lane == 31) wt[w] = inc;
    __syncthreads();
    if (threadIdx.x == 0) {
        int run = 0;
#pragma unroll
        for (int j = 0; j < 8; j++) { int t = wt[j]; wt[j] = run; run += t; }
    }
    __syncthreads();
    int excl = inc - c + wt[w] + g_bsum[blockIdx.x];
    if (i < NN) {
        g_rowptr[i] = excl;
        g_fill[i] = excl;
    }
}

__global__ void k_fillcsr4(const int4* __restrict__ src4, const int4* __restrict__ dst4) {
    int i = blockIdx.x * blockDim.x + threadIdx.x;
    if (i < NE / 4) {
        int4 d = dst4[i];
        int4 s = src4[i];
        int p0 = atomicAdd(&g_fill[d.x], 1);
        int p1 = atomicAdd(&g_fill[d.y], 1);
        int p2 = atomicAdd(&g_fill[d.z], 1);
        int p3 = atomicAdd(&g_fill[d.w], 1);
        g_csrc[p0] = s.x;
        g_csrc[p1] = s.y;
        g_csrc[p2] = s.z;
        g_csrc[p3] = s.w;
    }
}

// ---------------- TF32 warp-MMA GEMM, cp.async double-buffered + fused el/er ----------------
#define AS_CH 36
#define WS_CH 136
#define CHA (128 * AS_CH)
#define CHW (32 * WS_CH)
#define SMEM_FLOATS (2 * CHA + 2 * CHW)

__global__ void __launch_bounds__(256, 2)
k_gemm_mma(const float* __restrict__ A, const float* __restrict__ W,
           const float* __restrict__ al, const float* __restrict__ ar,
           float* __restrict__ C, int M) {
    extern __shared__ float sm[];
    float* AsB[2] = {sm, sm + CHA};
    float* WsB[2] = {sm + 2 * CHA, sm + 2 * CHA + CHW};
    __shared__ float s_al[DD], s_ar[DD];

    int tid = threadIdx.x;
    int wid = tid >> 5, lane = tid & 31;
    int g = lane >> 2, qa = lane & 3;
    int wr = wid >> 2, wc = wid & 3;
    int row0 = blockIdx.x * 128;

    if (tid < 128) {
        s_al[tid] = al[tid];
        s_ar[tid] = ar[tid];
    }

    uint32_t sAs[2], sWs[2];
#pragma unroll
    for (int b = 0; b < 2; b++) {
        sAs[b] = (uint32_t)__cvta_generic_to_shared(AsB[b]);
        sWs[b] = (uint32_t)__cvta_generic_to_shared(WsB[b]);
    }

    int am[4], af4[4], wk[4], wf4[4];
    bool avalid[4];
#pragma unroll
    for (int i = 0; i < 4; i++) {
        int idx = i * 256 + tid;
        am[i] = idx >> 3;  af4[i] = idx & 7;
        wk[i] = idx >> 5;  wf4[i] = idx & 31;
        avalid[i] = (row0 + am[i]) < M;
    }

    auto prefetch = [&](int c, int b) {
#pragma unroll
        for (int i = 0; i < 4; i++) {
            cp16(sAs[b] + (uint32_t)(am[i] * AS_CH + af4[i] * 4) * 4,
                 A + (size_t)(row0 + am[i]) * 128 + c * 32 + af4[i] * 4, avalid[i]);
            cp16(sWs[b] + (uint32_t)(wk[i] * WS_CH + wf4[i] * 4) * 4,
                 W + (size_t)(c * 32 + wk[i]) * 128 + wf4[i] * 4, true);
        }
        asm volatile("cp.async.commit_group;");
    };

    float acc[4][4][4];
#pragma unroll
    for (int i = 0; i < 4; i++)
#pragma unroll
        for (int j = 0; j < 4; j++)
#pragma unroll
            for (int k = 0; k < 4; k++) acc[i][j][k] = 0.f;

    prefetch(0, 0);
#pragma unroll
    for (int c = 0; c < 4; c++) {
        if (c < 3) prefetch(c + 1, (c + 1) & 1);
        if (c < 3) asm volatile("cp.async.wait_group 1;");
        else       asm volatile("cp.async.wait_group 0;");
        __syncthreads();
        const float* As = AsB[c & 1];
        const float* Ws = WsB[c & 1];
#pragma unroll
        for (int ks = 0; ks < 4; ks++) {
            int k0 = ks * 8;
            float af[4][4];
#pragma unroll
            for (int mf = 0; mf < 4; mf++) {
                const float* base = As + (wr * 64 + mf * 16 + g) * AS_CH + k0 + qa;
                af[mf][0] = totf32(base[0]);
                af[mf][1] = totf32(base[8 * AS_CH]);
                af[mf][2] = totf32(base[4]);
                af[mf][3] = totf32(base[8 * AS_CH + 4]);
            }
            float bf[4][2];
#pragma unroll
            for (int nf = 0; nf < 4; nf++) {
                const float* base = Ws + (k0 + qa) * WS_CH + wc * 32 + nf * 8 + g;
                bf[nf][0] = totf32(base[0]);
                bf[nf][1] = totf32(base[4 * WS_CH]);
            }
#pragma unroll
            for (int mf = 0; mf < 4; mf++)
#pragma unroll
                for (int nf = 0; nf < 4; nf++) {
                    asm volatile(
                        "mma.sync.aligned.m16n8k8.row.col.f32.tf32.tf32.f32 "
                        "{%0,%1,%2,%3}, {%4,%5,%6,%7}, {%8,%9}, {%0,%1,%2,%3};"
                        : "+f"(acc[mf][nf][0]), "+f"(acc[mf][nf][1]),
                          "+f"(acc[mf][nf][2]), "+f"(acc[mf][nf][3])
                        : "r"(__float_as_uint(af[mf][0])), "r"(__float_as_uint(af[mf][1])),
                          "r"(__float_as_uint(af[mf][2])), "r"(__float_as_uint(af[mf][3])),
                          "r"(__float_as_uint(bf[nf][0])), "r"(__float_as_uint(bf[nf][1])));
                }
        }
        __syncthreads();
    }

    float pel[8], per[8];
#pragma unroll
    for (int i = 0; i < 8; i++) { pel[i] = 0.f; per[i] = 0.f; }

#pragma unroll
    for (int mf = 0; mf < 4; mf++) {
        int r0 = row0 + wr * 64 + mf * 16 + g;
        int r1 = r0 + 8;
#pragma unroll
        for (int nf = 0; nf < 4; nf++) {
            int c = wc * 32 + nf * 8 + 2 * qa;
            float c0 = acc[mf][nf][0], c1 = acc[mf][nf][1];
            float c2 = acc[mf][nf][2], c3 = acc[mf][nf][3];
            float a0 = s_al[c], a1 = s_al[c + 1];
            float r0v = s_ar[c], r1v = s_ar[c + 1];
            pel[mf * 2 + 0] += c0 * a0 + c1 * a1;
            pel[mf * 2 + 1] += c2 * a0 + c3 * a1;
            per[mf * 2 + 0] += c0 * r0v + c1 * r1v;
            per[mf * 2 + 1] += c2 * r0v + c3 * r1v;
            if (r0 < M) *(float2*)(C + (size_t)r0 * 128 + c) = make_float2(c0, c1);
            if (r1 < M) *(float2*)(C + (size_t)r1 * 128 + c) = make_float2(c2, c3);
        }
    }
#pragma unroll
    for (int i = 0; i < 8; i++) {
#pragma unroll
        for (int o = 1; o <= 2; o <<= 1) {
            pel[i] += __shfl_xor_sync(0xFFFFFFFFu, pel[i], o);
            per[i] += __shfl_xor_sync(0xFFFFFFFFu, per[i], o);
        }
    }
    float* part_el = sm;
    float* part_er = sm + 512;
    __syncthreads();
    if (qa == 0) {
#pragma unroll
        for (int mf = 0; mf < 4; mf++) {
            int rl0 = wr * 64 + mf * 16 + g;
            part_el[rl0 * 4 + wc] = pel[mf * 2 + 0];
            part_el[(rl0 + 8) * 4 + wc] = pel[mf * 2 + 1];
            part_er[rl0 * 4 + wc] = per[mf * 2 + 0];
            part_er[(rl0 + 8) * 4 + wc] = per[mf * 2 + 1];
        }
    }
    __syncthreads();
    if (tid < 128 && row0 + tid < M) {
        float e = part_el[tid * 4] + part_el[tid * 4 + 1] + part_el[tid * 4 + 2] + part_el[tid * 4 + 3];
        float r = part_er[tid * 4] + part_er[tid * 4 + 1] + part_er[tid * 4 + 2] + part_er[tid * 4 + 3];
        g_el[row0 + tid] = e;
        g_er[row0 + tid] = r;
    }
}

// ---------------- single-pass (flash-style) warp-per-dst softmax + aggregation ----------------
// Online softmax state is warp-uniform (sv uniform per iteration); no shuffles needed.
__global__ void __launch_bounds__(256)
k_aggregate(const float* __restrict__ Wh, const float* __restrict__ bias,
            float* __restrict__ hout) {
    int lane = threadIdx.x & 31;
    int node = (blockIdx.x * blockDim.x + threadIdx.x) >> 5;
    if (node >= NN) return;
    int start = g_rowptr[node];
    int deg = g_rowptr[node + 1] - start;
    float erd = g_er[node];

    float m = -INFINITY, s = 0.f;
    float4 acc = make_float4(0.f, 0.f, 0.f, 0.f);
    const float4* Wh4 = (const float4*)Wh;

    int i = 0;
    for (; i + 4 <= deg; i += 4) {
        int sv0 = g_csrc[start + i + 0];
        int sv1 = g_csrc[start + i + 1];
        int sv2 = g_csrc[start + i + 2];
        int sv3 = g_csrc[start + i + 3];
        float e0 = lrelu(g_el[sv0] + erd);
        float e1 = lrelu(g_el[sv1] + erd);
        float e2 = lrelu(g_el[sv2] + erd);
        float e3 = lrelu(g_el[sv3] + erd);
        float nm = fmaxf(m, fmaxf(fmaxf(e0, e1), fmaxf(e2, e3)));
        float scale = __expf(m - nm);  // m=-inf first pass -> 0
        float a0 = __expf(e0 - nm);
        float a1 = __expf(e1 - nm);
        float a2 = __expf(e2 - nm);
        float a3 = __expf(e3 - nm);
        float4 w0 = Wh4[(size_t)sv0 * 32 + lane];
        float4 w1 = Wh4[(size_t)sv1 * 32 + lane];
        float4 w2 = Wh4[(size_t)sv2 * 32 + lane];
        float4 w3 = Wh4[(size_t)sv3 * 32 + lane];
        acc.x = acc.x * scale + a0 * w0.x + a1 * w1.x + a2 * w2.x + a3 * w3.x;
        acc.y = acc.y * scale + a0 * w0.y + a1 * w1.y + a2 * w2.y + a3 * w3.y;
        acc.z = acc.z * scale + a0 * w0.z + a1 * w1.z + a2 * w2.z + a3 * w3.z;
        acc.w = acc.w * scale + a0 * w0.w + a1 * w1.w + a2 * w2.w + a3 * w3.w;
        s = s * scale + (a0 + a1) + (a2 + a3);
        m = nm;
    }
    for (; i < deg; i++) {
        int sv = g_csrc[start + i];
        float e = lrelu(g_el[sv] + erd);
        float nm = fmaxf(m, e);
        float scale = __expf(m - nm);
        float a = __expf(e - nm);
        float4 wv = Wh4[(size_t)sv * 32 + lane];
        acc.x = acc.x * scale + a * wv.x;
        acc.y = acc.y * scale + a * wv.y;
        acc.z = acc.z * scale + a * wv.z;
        acc.w = acc.w * scale + a * wv.w;
        s = s * scale + a;
        m = nm;
    }
    float inv_s = (deg > 0) ? 1.f / s : 0.f;
    float4 b4 = ((const float4*)bias)[lane];
    float4 o;
    o.x = eluf(acc.x * inv_s + b4.x);
    o.y = eluf(acc.y * inv_s + b4.y);
    o.z = eluf(acc.z * inv_s + b4.z);
    o.w = eluf(acc.w * inv_s + b4.w);
    ((float4*)hout)[(size_t)node * 32 + lane] = o;
}

// ---------------- graph pooling + classifier ----------------
__global__ void k_bounds(const int* __restrict__ gid) {
    int g = threadIdx.x;
    if (g > NG) return;
    int lo = 0, hi = NN;
    while (lo < hi) {
        int mid = (lo + hi) >> 1;
        if (gid[mid] < g) lo = mid + 1; else hi = mid;
    }
    g_gstart[g] = lo;
}

__global__ void k_pool(const float* __restrict__ h) {
    int g = blockIdx.x;
    int t = threadIdx.x;
    int st = g_gstart[g], en = g_gstart[g + 1];
    float s0 = 0.f, s1 = 0.f, s2 = 0.f, s3 = 0.f;
    int i = st;
    for (; i + 4 <= en; i += 4) {
        s0 += h[(size_t)(i + 0) * DD + t];
        s1 += h[(size_t)(i + 1) * DD + t];
        s2 += h[(size_t)(i + 2) * DD + t];
        s3 += h[(size_t)(i + 3) * DD + t];
    }
    for (; i < en; i++) s0 += h[(size_t)i * DD + t];
    float s = (s0 + s1) + (s2 + s3);
    int c = en - st;
    g_hg[g * DD + t] = s / (float)max(c, 1);
}

__global__ void k_classify(const float* __restrict__ Wc, const float* __restrict__ bc,
                           float* __restrict__ out) {
    int t = threadIdx.x;
    if (t >= NG * NC) return;
    int g = t >> 1, c = t & 1;
    float s = 0.f;
#pragma unroll 4
    for (int k = 0; k < DD; k++) s += g_hg[g * DD + k] * Wc[k * NC + c];
    out[g * NC + c] = s + bc[c];
}

// ---------------- launch (single stream) ----------------
extern "C" void kernel_launch(void* const* d_in, const int* in_sizes, int n_in,
                              void* d_out, int out_size) {
    const float* x = (const float*)d_in[0];
    const int* src = (const int*)d_in[1];
    const int* dst = (const int*)d_in[2];
    const int* gid = (const int*)d_in[3];
    const float* W[3]  = {(const float*)d_in[4],  (const float*)d_in[8],  (const float*)d_in[12]};
    const float* al[3] = {(const float*)d_in[5],  (const float*)d_in[9],  (const float*)d_in[13]};
    const float* ar[3] = {(const float*)d_in[6],  (const float*)d_in[10], (const float*)d_in[14]};
    const float* bb[3] = {(const float*)d_in[7],  (const float*)d_in[11], (const float*)d_in[15]};
    const float* Wc = (const float*)d_in[16];
    const float* bc = (const float*)d_in[17];
    float* out = (float*)d_out;

    float *pWh, *phA, *phB;
    int* pcnt;
    cudaGetSymbolAddress((void**)&pWh, g_Wh);
    cudaGetSymbolAddress((void**)&phA, g_hA);
    cudaGetSymbolAddress((void**)&phB, g_hB);
    cudaGetSymbolAddress((void**)&pcnt, g_cnt);

    static bool attr_set = false;
    if (!attr_set) {
        cudaFuncSetAttribute(k_gemm_mma, cudaFuncAttributeMaxDynamicSharedMemorySize,
                             SMEM_FLOATS * sizeof(float));
        attr_set = true;
    }

    // CSR build
    cudaMemsetAsync(pcnt, 0, NN * sizeof(int));
    const int eg4 = (NE / 4 + 255) / 256;
    k_hist4<<<eg4, 256>>>((const int4*)dst);
    k_scan1<<<NBLK, 256>>>();
    k_scan2<<<1, 256>>>();
    k_scan3<<<NBLK, 256>>>();
    k_fillcsr4<<<eg4, 256>>>((const int4*)src, (const int4*)dst);

    const int warpGrid = (NN * 32 + 255) / 256;
    const int gemmGrid = (NN + 127) / 128;
    const float* hin = x;
    float* bufs[2] = {phA, phB};
    for (int l = 0; l < 3; l++) {
        k_gemm_mma<<<gemmGrid, 256, SMEM_FLOATS * sizeof(float)>>>(hin, W[l], al[l], ar[l], pWh, NN);
        k_aggregate<<<warpGrid, 256>>>(pWh, bb[l], bufs[l & 1]);
        hin = bufs[l & 1];
    }

    k_bounds<<<1, 128>>>(gid);
    k_pool<<<NG, 128>>>(hin);
    k_classify<<<1, 128>>>(Wc, bc, out);
}